// round 1
// baseline (speedup 1.0000x reference)
#include <cuda_runtime.h>
#include <math.h>

#define NHEAD 8
#define HDIM  32
#define CIN   256
#define WS    7
#define WT    49          // tokens per window
#define QKVN  768

// smem layout (floats):
//   xs   [51][256]            (padded rows 49,50 = 0; reused as attn_out[49][256])
//   q_s  [8][49][32]
//   kT_s [8][32][49]
//   v_s  [8][49][32]
//   pos_s[169]
//   idx_s[49] (int)
#define XS_ROWS 51
#define SMEM_FLOATS (XS_ROWS*256 + 3*NHEAD*WT*HDIM + 169)
#define SMEM_BYTES  (SMEM_FLOATS*4 + WT*4)

__global__ __launch_bounds__(256, 1)
void swin_mhsa_fused_kernel(const float* __restrict__ x,
                            const float* __restrict__ pos,
                            const float* __restrict__ w_qkv,
                            const float* __restrict__ b_qkv,
                            const float* __restrict__ w_out,
                            const float* __restrict__ b_out,
                            float* __restrict__ out)
{
    extern __shared__ float smem[];
    float* xs   = smem;                              // [51][256]
    float* q_s  = xs   + XS_ROWS*256;                // [8][49][32]
    float* kT_s = q_s  + NHEAD*WT*HDIM;              // [8][32][49]
    float* v_s  = kT_s + NHEAD*HDIM*WT;              // [8][49][32]
    float* pos_s = v_s + NHEAD*WT*HDIM;              // [169]
    int*   idx_s = (int*)(pos_s + 169);              // [49]

    const int tid = threadIdx.x;
    const int win = blockIdx.x;
    const int b  = win >> 6;
    const int wi = (win >> 3) & 7;
    const int wj = win & 7;

    // base offset of window token (0,0) in x / out (both [B,56,56,256])
    const long base = ((long)(b*56 + wi*WS) * 56 + wj*WS) * 256;

    // ---------------- Phase 1: load x tile ----------------
    {
        const int lane64 = tid & 63;          // float4 index within a row (64 * 16B = 1KB row)
        for (int t = tid >> 6; t < WT; t += 4) {
            const float4* src = (const float4*)(x + base + ((long)(t/WS)*56 + (t%WS))*256);
            ((float4*)(xs + t*256))[lane64] = src[lane64];
        }
        // zero pad rows 49,50
        xs[49*256 + tid] = 0.f;
        xs[50*256 + tid] = 0.f;
        if (tid < 169) pos_s[tid] = pos[tid];
        if (tid < WT)  idx_s[tid] = tid/WS + tid%WS;   // in [0,12]
    }
    __syncthreads();

    // ---------------- Phase 2: QKV GEMM (M=49, N=768, K=256) ----------------
    // thread tid owns output columns {tid, tid+256, tid+512} = (q,k,v) for head h=tid/32, dim d=tid%32
    const int hh = tid >> 5, dd = tid & 31;
    {
        const float bq = b_qkv[tid];
        const float bk = b_qkv[tid + 256];
        const float bv = b_qkv[tid + 512];
        #pragma unroll 1
        for (int p = 0; p < 3; ++p) {
            const int t0 = p * 17;            // rows t0..t0+16 (pad rows harmless)
            float accq[17], acck[17], accv[17];
            #pragma unroll
            for (int i = 0; i < 17; ++i) { accq[i]=0.f; acck[i]=0.f; accv[i]=0.f; }
            #pragma unroll 2
            for (int k = 0; k < CIN; ++k) {
                const float w0 = w_qkv[k*QKVN + tid];
                const float w1 = w_qkv[k*QKVN + tid + 256];
                const float w2 = w_qkv[k*QKVN + tid + 512];
                #pragma unroll
                for (int i = 0; i < 17; ++i) {
                    const float xv = xs[(t0+i)*256 + k];
                    accq[i] = fmaf(xv, w0, accq[i]);
                    acck[i] = fmaf(xv, w1, acck[i]);
                    accv[i] = fmaf(xv, w2, accv[i]);
                }
            }
            #pragma unroll
            for (int i = 0; i < 17; ++i) {
                const int t = t0 + i;
                if (t < WT) {
                    q_s [(hh*WT + t)*HDIM + dd] = accq[i] + bq;
                    kT_s[(hh*HDIM + dd)*WT + t] = acck[i] + bk;   // transposed for phase 3
                    v_s [(hh*WT + t)*HDIM + dd] = accv[i] + bv;
                }
            }
        }
    }
    __syncthreads();

    // ---------------- Phase 3: windowed attention, one warp per head ----------------
    {
        const int lane = tid & 31;
        const int h    = tid >> 5;           // 8 warps == 8 heads
        const float* qh  = q_s  + h*WT*HDIM;
        const float* kTh = kT_s + h*HDIM*WT;
        const float* vh  = v_s  + h*WT*HDIM;
        const int j1 = lane;
        const int j2 = (lane < 17) ? lane + 32 : 0;   // clamped; masked below
        const float SQ = 5.6568542494923806f;         // sqrt(32)  (reference MULTIPLIES)
        const int ij1 = idx_s[j1];
        const int ij2 = idx_s[j2];

        for (int qt = 0; qt < WT; ++qt) {
            float s0 = 0.f, s1 = 0.f;
            #pragma unroll 8
            for (int d = 0; d < HDIM; ++d) {
                const float qv = qh[qt*HDIM + d];
                s0 = fmaf(qv, kTh[d*WT + j1], s0);
                s1 = fmaf(qv, kTh[d*WT + j2], s1);
            }
            const int iq13 = idx_s[qt] * 13;
            s0 = s0 * SQ + pos_s[iq13 + ij1];
            s1 = (lane < 17) ? (s1 * SQ + pos_s[iq13 + ij2]) : -1e30f;

            // softmax over 49 keys
            float m = fmaxf(s0, s1);
            #pragma unroll
            for (int o = 16; o; o >>= 1) m = fmaxf(m, __shfl_xor_sync(0xFFFFFFFFu, m, o));
            const float e0 = expf(s0 - m);
            const float e1 = (lane < 17) ? expf(s1 - m) : 0.f;
            float sum = e0 + e1;
            #pragma unroll
            for (int o = 16; o; o >>= 1) sum += __shfl_xor_sync(0xFFFFFFFFu, sum, o);
            const float inv = 1.f / sum;
            const float p0 = e0 * inv;
            const float p1 = e1 * inv;

            // out[qt][lane] = sum_j p_j * v[j][lane]   (lane == head-dim)
            float o_acc = 0.f;
            #pragma unroll
            for (int j = 0; j < 32; ++j) {
                const float pj = __shfl_sync(0xFFFFFFFFu, p0, j);
                o_acc = fmaf(pj, vh[j*HDIM + lane], o_acc);
            }
            #pragma unroll
            for (int j = 0; j < 17; ++j) {
                const float pj = __shfl_sync(0xFFFFFFFFu, p1, j);
                o_acc = fmaf(pj, vh[(j+32)*HDIM + lane], o_acc);
            }
            xs[qt*256 + h*HDIM + lane] = o_acc;   // attn_out reuses xs
        }
    }
    __syncthreads();

    // ---------------- Phase 4: output projection (M=49, N=256, K=256) ----------------
    {
        const float bo = b_out[tid];
        #pragma unroll 1
        for (int p = 0; p < 2; ++p) {
            const int t0 = p * 25;           // rows t0..t0+24 (row 49 is zero pad)
            float acc[25];
            #pragma unroll
            for (int i = 0; i < 25; ++i) acc[i] = 0.f;
            #pragma unroll 2
            for (int k = 0; k < CIN; ++k) {
                const float w = w_out[k*256 + tid];
                #pragma unroll
                for (int i = 0; i < 25; ++i)
                    acc[i] = fmaf(xs[(t0+i)*256 + k], w, acc[i]);
            }
            #pragma unroll
            for (int i = 0; i < 25; ++i) {
                const int t = t0 + i;
                if (t < WT)
                    out[base + ((long)(t/WS)*56 + (t%WS))*256 + tid] = acc[i] + bo;
            }
        }
    }
}

extern "C" void kernel_launch(void* const* d_in, const int* in_sizes, int n_in,
                              void* d_out, int out_size)
{
    const float* x      = (const float*)d_in[0];
    const float* pos    = (const float*)d_in[1];
    const float* w_qkv  = (const float*)d_in[2];
    const float* b_qkv  = (const float*)d_in[3];
    const float* w_out  = (const float*)d_in[4];
    const float* b_out  = (const float*)d_in[5];
    float* out = (float*)d_out;

    cudaFuncSetAttribute(swin_mhsa_fused_kernel,
                         cudaFuncAttributeMaxDynamicSharedMemorySize, SMEM_BYTES);
    swin_mhsa_fused_kernel<<<4096, 256, SMEM_BYTES>>>(x, pos, w_qkv, b_qkv, w_out, b_out, out);
}

// round 2
// speedup vs baseline: 1.3600x; 1.3600x over previous
#include <cuda_runtime.h>

#define NHEAD 8
#define HDIM  32
#define CIN   256
#define WS    7
#define WT    49
#define QKVN  768
#define TP    52      // padded token dimension (tokens 49..51 are zero pads)
#define NP    25      // packed token-pairs per column (50 tokens)

// smem floats:
//   xs_T [256][52]   = 13312   (x transposed; later reused as attn_out transposed)
//   qT   [8][32][52] = 13312
//   kT   [8][32][52] = 13312
//   v_s  [8][50][32] = 12800
//   pos  [169]
#define SMEM_FLOATS (13312*3 + 12800 + 169)
#define SMEM_BYTES  (SMEM_FLOATS*4)

// ---- packed f32x2 helpers (FFMA2 only reachable via PTX) ----
__device__ __forceinline__ unsigned long long ffma2(unsigned long long a,
                                                    unsigned long long b,
                                                    unsigned long long c) {
    unsigned long long d;
    asm("fma.rn.f32x2 %0, %1, %2, %3;" : "=l"(d) : "l"(a), "l"(b), "l"(c));
    return d;
}
__device__ __forceinline__ unsigned long long dup2(float x) {
    unsigned long long d; unsigned u = __float_as_uint(x);
    asm("mov.b64 %0, {%1, %2};" : "=l"(d) : "r"(u), "r"(u));
    return d;
}
__device__ __forceinline__ float2 unpk(unsigned long long a) {
    unsigned lo, hi;
    asm("mov.b64 {%0, %1}, %2;" : "=r"(lo), "=r"(hi) : "l"(a));
    return make_float2(__uint_as_float(lo), __uint_as_float(hi));
}

__global__ __launch_bounds__(256, 1)
void swin_mhsa_f32x2_kernel(const float* __restrict__ x,
                            const float* __restrict__ pos,
                            const float* __restrict__ w_qkv,
                            const float* __restrict__ b_qkv,
                            const float* __restrict__ w_out,
                            const float* __restrict__ b_out,
                            float* __restrict__ out)
{
    extern __shared__ float smem[];
    float* xs_T  = smem;                 // [256][52]
    float* qT    = xs_T + 13312;         // [8][32][52]
    float* kT    = qT   + 13312;         // [8][32][52]
    float* v_s   = kT   + 13312;         // [8][50][32]
    float* pos_s = v_s  + 12800;         // [169]

    const int tid = threadIdx.x;
    const int win = blockIdx.x;
    const int b  = win >> 6;
    const int wi = (win >> 3) & 7;
    const int wj = win & 7;
    const long base = ((long)(b*56 + wi*WS) * 56 + wj*WS) * 256;

    // ---------------- Phase 1: load x transposed ----------------
    {
        if (tid < 169) pos_s[tid] = pos[tid];
        float* xrow = xs_T + tid * TP;     // channel row for channel c = tid
        #pragma unroll
        for (int t = 0; t < WT; ++t) {
            const int off = (t/WS)*56 + (t%WS);
            xrow[t] = x[base + (long)off*256 + tid];
        }
        xrow[49] = 0.f; xrow[50] = 0.f; xrow[51] = 0.f;
    }
    __syncthreads();

    // ---------------- Phase 2: QKV GEMM with packed f32x2 ----------------
    // 3 passes: p=0 -> q, p=1 -> k, p=2 -> v. Thread owns column (p*256 + tid).
    {
        #pragma unroll 1
        for (int p = 0; p < 3; ++p) {
            const int col = p * 256 + tid;
            unsigned long long acc[NP];
            const unsigned long long binit = dup2(b_qkv[col]);
            #pragma unroll
            for (int i = 0; i < NP; ++i) acc[i] = binit;

            const float* wp = w_qkv + col;
            const float* xr = xs_T;
            #pragma unroll 2
            for (int k = 0; k < CIN; ++k) {
                const unsigned long long wd = dup2(wp[k*QKVN]);
                const ulonglong2* xv = (const ulonglong2*)(xr + k*TP);
                #pragma unroll
                for (int i = 0; i < 12; ++i) {
                    const ulonglong2 u = xv[i];
                    acc[2*i]   = ffma2(u.x, wd, acc[2*i]);
                    acc[2*i+1] = ffma2(u.y, wd, acc[2*i+1]);
                }
                acc[24] = ffma2(((const unsigned long long*)xv)[24], wd, acc[24]);
            }

            if (p < 2) {
                // q/k stored transposed: row = (h*32+d)*52 = tid*52, tokens contiguous
                unsigned long long* dst = (unsigned long long*)((p ? kT : qT) + tid*TP);
                #pragma unroll
                for (int i = 0; i < NP; ++i) dst[i] = acc[i];
            } else {
                // v stored [h][t][32]
                float* vb = v_s + (tid >> 5) * 50 * HDIM + (tid & 31);
                #pragma unroll
                for (int i = 0; i < NP; ++i) {
                    const float2 f = unpk(acc[i]);
                    vb[(2*i)  *HDIM] = f.x;
                    vb[(2*i+1)*HDIM] = f.y;
                }
            }
        }
    }
    __syncthreads();

    // ---------------- Phase 3: windowed attention (one warp per head) ----------------
    {
        const int lane = tid & 31;
        const int h    = tid >> 5;
        const float* qTh = qT  + h*HDIM*TP;
        const float* kTh = kT  + h*HDIM*TP;
        const float* vh  = v_s + h*50*HDIM;

        const int j1 = lane;
        const bool has2 = (lane < 17);
        const int j2 = has2 ? lane + 32 : 0;

        // hoist keys into registers: removes 64 LDS per query token
        float kk1[HDIM], kk2[HDIM];
        #pragma unroll
        for (int d = 0; d < HDIM; ++d) {
            kk1[d] = kTh[d*TP + j1];
            kk2[d] = kTh[d*TP + j2];
        }
        const int ij1 = j1/WS + j1%WS;
        const int ij2 = j2/WS + j2%WS;
        const float SQ = 5.6568542494923806f;   // sqrt(32), reference MULTIPLIES

        int qi = 0, qj = 0;
        for (int qt = 0; qt < WT; ++qt) {
            float s0 = 0.f, s1 = 0.f;
            #pragma unroll
            for (int d = 0; d < HDIM; ++d) {
                const float qv = qTh[d*TP + qt];   // broadcast
                s0 = fmaf(qv, kk1[d], s0);
                s1 = fmaf(qv, kk2[d], s1);
            }
            const int iq13 = (qi + qj) * 13;
            if (++qj == WS) { qj = 0; ++qi; }
            s0 = s0 * SQ + pos_s[iq13 + ij1];
            s1 = has2 ? (s1 * SQ + pos_s[iq13 + ij2]) : -1e30f;

            float m = fmaxf(s0, s1);
            #pragma unroll
            for (int o = 16; o; o >>= 1) m = fmaxf(m, __shfl_xor_sync(0xFFFFFFFFu, m, o));
            const float e0 = __expf(s0 - m);
            const float e1 = has2 ? __expf(s1 - m) : 0.f;
            float sum = e0 + e1;
            #pragma unroll
            for (int o = 16; o; o >>= 1) sum += __shfl_xor_sync(0xFFFFFFFFu, sum, o);
            const float inv = __fdividef(1.f, sum);
            const float p0 = e0 * inv;
            const float p1 = e1 * inv;

            float o_acc = 0.f;
            #pragma unroll
            for (int j = 0; j < 32; ++j) {
                const float pj = __shfl_sync(0xFFFFFFFFu, p0, j);
                o_acc = fmaf(pj, vh[j*HDIM + lane], o_acc);
            }
            #pragma unroll
            for (int j = 0; j < 17; ++j) {
                const float pj = __shfl_sync(0xFFFFFFFFu, p1, j);
                o_acc = fmaf(pj, vh[(j+32)*HDIM + lane], o_acc);
            }
            // attn_out transposed into xs_T: channel = h*32+lane = tid-of-this-thread
            xs_T[(h*HDIM + lane)*TP + qt] = o_acc;
        }
    }
    __syncthreads();

    // ---------------- Phase 4: output projection with packed f32x2 ----------------
    {
        unsigned long long acc[NP];
        const unsigned long long binit = dup2(b_out[tid]);
        #pragma unroll
        for (int i = 0; i < NP; ++i) acc[i] = binit;

        const float* wp = w_out + tid;
        #pragma unroll 2
        for (int k = 0; k < CIN; ++k) {
            const unsigned long long wd = dup2(wp[k*256]);
            const ulonglong2* xv = (const ulonglong2*)(xs_T + k*TP);
            #pragma unroll
            for (int i = 0; i < 12; ++i) {
                const ulonglong2 u = xv[i];
                acc[2*i]   = ffma2(u.x, wd, acc[2*i]);
                acc[2*i+1] = ffma2(u.y, wd, acc[2*i+1]);
            }
            acc[24] = ffma2(((const unsigned long long*)xv)[24], wd, acc[24]);
        }

        #pragma unroll
        for (int i = 0; i < NP; ++i) {
            const float2 f = unpk(acc[i]);
            {
                const int t = 2*i;
                const int off = (t/WS)*56 + (t%WS);
                out[base + (long)off*256 + tid] = f.x;
            }
            if (2*i + 1 < WT) {
                const int t = 2*i + 1;
                const int off = (t/WS)*56 + (t%WS);
                out[base + (long)off*256 + tid] = f.y;
            }
        }
    }
}

extern "C" void kernel_launch(void* const* d_in, const int* in_sizes, int n_in,
                              void* d_out, int out_size)
{
    const float* x      = (const float*)d_in[0];
    const float* pos    = (const float*)d_in[1];
    const float* w_qkv  = (const float*)d_in[2];
    const float* b_qkv  = (const float*)d_in[3];
    const float* w_out  = (const float*)d_in[4];
    const float* b_out  = (const float*)d_in[5];
    float* out = (float*)d_out;

    cudaFuncSetAttribute(swin_mhsa_f32x2_kernel,
                         cudaFuncAttributeMaxDynamicSharedMemorySize, SMEM_BYTES);
    swin_mhsa_f32x2_kernel<<<4096, 256, SMEM_BYTES>>>(x, pos, w_qkv, b_qkv, w_out, b_out, out);
}

// round 6
// speedup vs baseline: 2.1569x; 1.5859x over previous
#include <cuda_runtime.h>
#include <cuda_bf16.h>
#include <cstdint>

#define TOK   200704            // 64*56*56 tokens
#define CDIM  256
#define QKVN  768
#define WS    7
#define WT    49
#define NHEAD 8
#define HDIM  32

// ------------------------- scratch (device globals) -------------------------
__device__ float          g_qkv[154140672];          // [TOK][768] fp32
__device__ __nv_bfloat16  g_xh [51380224];           // [TOK][256] x hi
__device__ __nv_bfloat16  g_xl [51380224];           // [TOK][256] x lo
__device__ __nv_bfloat16  g_ah [51380224];           // attn out hi
__device__ __nv_bfloat16  g_al [51380224];           // attn out lo
__device__ __nv_bfloat16  g_wqT_h[196608];           // WqkvT [768][256] K-major
__device__ __nv_bfloat16  g_wqT_l[196608];
__device__ __nv_bfloat16  g_woT_h[65536];            // WoutT [256][256] K-major
__device__ __nv_bfloat16  g_woT_l[65536];

// ------------------------- helpers -------------------------
__device__ __forceinline__ uint32_t smem_u32(const void* p) {
    uint32_t a;
    asm("{ .reg .u64 t; cvta.to.shared.u64 t, %1; cvt.u32.u64 %0, t; }" : "=r"(a) : "l"(p));
    return a;
}
#define CP_ASYNC16(dst, src) \
    asm volatile("cp.async.cg.shared.global [%0], [%1], 16;\n" :: "r"(dst), "l"(src))
#define CP_COMMIT() asm volatile("cp.async.commit_group;\n" ::: "memory")

__device__ __forceinline__ void ldsm4(uint32_t addr, uint32_t* r) {
    asm volatile("ldmatrix.sync.aligned.m8n8.x4.shared.b16 {%0,%1,%2,%3}, [%4];"
        : "=r"(r[0]), "=r"(r[1]), "=r"(r[2]), "=r"(r[3]) : "r"(addr));
}
__device__ __forceinline__ void mma16816(float* c, const uint32_t* a, const uint32_t* b) {
    asm volatile(
        "mma.sync.aligned.m16n8k16.row.col.f32.bf16.bf16.f32 "
        "{%0,%1,%2,%3}, {%4,%5,%6,%7}, {%8,%9}, {%0,%1,%2,%3};"
        : "+f"(c[0]), "+f"(c[1]), "+f"(c[2]), "+f"(c[3])
        : "r"(a[0]), "r"(a[1]), "r"(a[2]), "r"(a[3]), "r"(b[0]), "r"(b[1]));
}
__device__ __forceinline__ uint32_t sw128(uint32_t row, uint32_t kb) {
    uint32_t off = (row << 7) + kb;
    return off ^ ((off >> 3) & 0x70);
}
__device__ __forceinline__ void split2(float v, __nv_bfloat16& h, __nv_bfloat16& l) {
    h = __float2bfloat16_rn(v);
    l = __float2bfloat16_rn(v - __bfloat162float(h));
}

// ------------------------- P0: split kernels -------------------------
__global__ void split_x_kernel(const float* __restrict__ x) {
    size_t n4 = (size_t)TOK * CDIM / 4;
    for (size_t i = (size_t)blockIdx.x * blockDim.x + threadIdx.x; i < n4;
         i += (size_t)gridDim.x * blockDim.x) {
        float4 v = ((const float4*)x)[i];
        __nv_bfloat16 h0,h1,h2,h3,l0,l1,l2,l3;
        split2(v.x,h0,l0); split2(v.y,h1,l1); split2(v.z,h2,l2); split2(v.w,h3,l3);
        ((__nv_bfloat162*)g_xh)[2*i]   = __nv_bfloat162(h0,h1);
        ((__nv_bfloat162*)g_xh)[2*i+1] = __nv_bfloat162(h2,h3);
        ((__nv_bfloat162*)g_xl)[2*i]   = __nv_bfloat162(l0,l1);
        ((__nv_bfloat162*)g_xl)[2*i+1] = __nv_bfloat162(l2,l3);
    }
}
// out[n*256 + k] = split(w[k*N + n])   (transpose to [N][K] K-major)
__global__ void split_wT_kernel(const float* __restrict__ w,
                                __nv_bfloat16* __restrict__ oh,
                                __nv_bfloat16* __restrict__ ol, int N) {
    int idx = blockIdx.x * blockDim.x + threadIdx.x;
    if (idx >= N * CDIM) return;
    int n = idx >> 8, k = idx & 255;
    __nv_bfloat16 h, l;
    split2(w[(size_t)k * N + n], h, l);
    oh[(size_t)n * CDIM + k] = h;
    ol[(size_t)n * CDIM + k] = l;
}

// ------------------------- split-bf16 GEMM on mma.sync -------------------------
// C[M,N] = A[M,256] @ B[N,256]^T, tiles 128x128, K-chunks of 64, 3-stage cp.async.
#define BM 128
#define BN 128
#define BK 64
#define NSTAGE 3
#define AH_OFF 0
#define AL_OFF 16384
#define BH_OFF 32768
#define BL_OFF 49152
#define STAGE_BYTES 65536
#define GEMM_SMEM (NSTAGE * STAGE_BYTES)

__device__ __forceinline__ void load_chunk(uint32_t sb, int c,
    const __nv_bfloat16* __restrict__ Ah, const __nv_bfloat16* __restrict__ Al,
    const __nv_bfloat16* __restrict__ Bh, const __nv_bfloat16* __restrict__ Bl,
    int m0, int n0, int tid)
{
    #pragma unroll
    for (int i = 0; i < 4; ++i) {
        int t = tid + i * 256, r = t >> 3, seg = t & 7;
        uint32_t dst = sb + sw128(r, seg * 16);
        size_t ga = (size_t)(m0 + r) * CDIM + c * BK + seg * 8;
        CP_ASYNC16(dst + AH_OFF, Ah + ga);
        CP_ASYNC16(dst + AL_OFF, Al + ga);
        size_t gb = (size_t)(n0 + r) * CDIM + c * BK + seg * 8;
        CP_ASYNC16(dst + BH_OFF, Bh + gb);
        CP_ASYNC16(dst + BL_OFF, Bl + gb);
    }
    CP_COMMIT();
}

__global__ __launch_bounds__(256, 1)
void gemm_split_kernel(const __nv_bfloat16* __restrict__ Ah, const __nv_bfloat16* __restrict__ Al,
                       const __nv_bfloat16* __restrict__ Bh, const __nv_bfloat16* __restrict__ Bl,
                       const float* __restrict__ bias, float* __restrict__ outp, int out_ld)
{
    extern __shared__ __align__(1024) char smem[];
    const uint32_t smb = smem_u32(smem);
    const int tid  = threadIdx.x;
    const int lane = tid & 31, wid = tid >> 5;
    const int wm = wid & 3, wn = wid >> 2;              // 4 M-warps x 2 N-warps
    const int n0 = blockIdx.x * BN;
    const int m0 = blockIdx.y * BM;

    const int li = lane & 7, lg = lane >> 3;
    // ldmatrix lane-row/col-offset components
    const int aRowOff = ((lg & 1) << 3) + li;           // + (g&1)*8 + i
    const int aKoff   = (lg >> 1) << 4;                 // + (g>>1)*16 bytes
    const int bRowOff = ((lg >> 1) << 3) + li;          // + (g>>1)*8 + i
    const int bKoff   = (lg & 1) << 4;                  // + (g&1)*16 bytes

    float acc[2][8][4];
    #pragma unroll
    for (int a = 0; a < 2; ++a)
        #pragma unroll
        for (int b = 0; b < 8; ++b)
            #pragma unroll
            for (int cc = 0; cc < 4; ++cc) acc[a][b][cc] = 0.f;

    // prologue
    load_chunk(smb + 0 * STAGE_BYTES, 0, Ah, Al, Bh, Bl, m0, n0, tid);
    load_chunk(smb + 1 * STAGE_BYTES, 1, Ah, Al, Bh, Bl, m0, n0, tid);

    #pragma unroll 1
    for (int c = 0; c < 4; ++c) {
        if (c < 3) asm volatile("cp.async.wait_group 1;\n" ::: "memory");
        else       asm volatile("cp.async.wait_group 0;\n" ::: "memory");
        __syncthreads();
        const uint32_t sb = smb + (uint32_t)(c % NSTAGE) * STAGE_BYTES;

        #pragma unroll
        for (int s = 0; s < 4; ++s) {                    // 4 x k16 steps
            const uint32_t kbA = (uint32_t)(s * 32 + aKoff);
            const uint32_t kbB = (uint32_t)(s * 32 + bKoff);
            uint32_t ah[2][4], al[2][4];
            #pragma unroll
            for (int mt = 0; mt < 2; ++mt) {
                const uint32_t arow = (uint32_t)(wm * 32 + mt * 16 + aRowOff);
                const uint32_t sw = sw128(arow, kbA);
                ldsm4(sb + AH_OFF + sw, ah[mt]);
                ldsm4(sb + AL_OFF + sw, al[mt]);
            }
            uint32_t bh[4][4], bl[4][4];
            #pragma unroll
            for (int nt = 0; nt < 4; ++nt) {
                const uint32_t brow = (uint32_t)(wn * 64 + nt * 16 + bRowOff);
                const uint32_t sw = sw128(brow, kbB);
                ldsm4(sb + BH_OFF + sw, bh[nt]);
                ldsm4(sb + BL_OFF + sw, bl[nt]);
            }
            #pragma unroll
            for (int mt = 0; mt < 2; ++mt)
                #pragma unroll
                for (int nt = 0; nt < 4; ++nt) {
                    mma16816(acc[mt][nt*2],   ah[mt], &bh[nt][0]);
                    mma16816(acc[mt][nt*2],   ah[mt], &bl[nt][0]);
                    mma16816(acc[mt][nt*2],   al[mt], &bh[nt][0]);
                    mma16816(acc[mt][nt*2+1], ah[mt], &bh[nt][2]);
                    mma16816(acc[mt][nt*2+1], ah[mt], &bl[nt][2]);
                    mma16816(acc[mt][nt*2+1], al[mt], &bh[nt][2]);
                }
        }
        if (c + 2 < 4)
            load_chunk(smb + (uint32_t)((c + 2) % NSTAGE) * STAGE_BYTES, c + 2,
                       Ah, Al, Bh, Bl, m0, n0, tid);
    }

    // epilogue: fragment (mt,nt8): c0,c1 @ (row, col..col+1); c2,c3 @ (row+8, ...)
    #pragma unroll
    for (int mt = 0; mt < 2; ++mt) {
        const int row = m0 + wm * 32 + mt * 16 + (lane >> 2);
        #pragma unroll
        for (int nt = 0; nt < 8; ++nt) {
            const int col = n0 + wn * 64 + nt * 8 + 2 * (lane & 3);
            const float b0 = __ldg(bias + col), b1 = __ldg(bias + col + 1);
            float2 v0 = make_float2(acc[mt][nt][0] + b0, acc[mt][nt][1] + b1);
            float2 v1 = make_float2(acc[mt][nt][2] + b0, acc[mt][nt][3] + b1);
            *(float2*)(outp + (size_t)row * out_ld + col)       = v0;
            *(float2*)(outp + (size_t)(row + 8) * out_ld + col) = v1;
        }
    }
}

// ------------------------- K2: windowed attention -------------------------
#define TP 52
#define ATT_SMEM ((13312 + 13312 + 12544 + 169 + 7) * 4)

__global__ __launch_bounds__(256, 1)
void attn_kernel(const float* __restrict__ pos)
{
    extern __shared__ float smf[];
    float* qT    = smf;                 // [8*32][52]
    float* kT    = qT + 13312;
    float* v_s   = kT + 13312;          // [8][49][32]
    float* pos_s = v_s + 12544;         // [169]

    const int tid = threadIdx.x;
    const int h = tid >> 5, d = tid & 31;
    const int win = blockIdx.x;
    const int b = win >> 6, wi = (win >> 3) & 7, wj = win & 7;
    const int base_tok = b * 3136 + (wi * WS) * 56 + wj * WS;

    if (tid < 169) pos_s[tid] = pos[tid];
    #pragma unroll 7
    for (int t = 0; t < WT; ++t) {
        const int row = base_tok + (t / WS) * 56 + (t % WS);
        const float* rp = g_qkv + (size_t)row * QKVN;
        qT[tid * TP + t] = rp[tid];
        kT[tid * TP + t] = rp[256 + tid];
        v_s[(h * WT + t) * HDIM + d] = rp[512 + tid];
    }
    __syncthreads();

    const int lane = d;
    const float* qTh = qT + h * HDIM * TP;
    const float* kTh = kT + h * HDIM * TP;
    const float* vh  = v_s + h * WT * HDIM;

    const int j1 = lane;
    const bool has2 = (lane < 17);
    const int j2 = has2 ? lane + 32 : 0;

    float kk1[HDIM], kk2[HDIM];
    #pragma unroll
    for (int dd = 0; dd < HDIM; ++dd) {
        kk1[dd] = kTh[dd * TP + j1];
        kk2[dd] = kTh[dd * TP + j2];
    }
    const int ij1 = j1 / WS + j1 % WS;
    const int ij2 = j2 / WS + j2 % WS;
    const float SQ = 5.6568542494923806f;   // sqrt(32), reference multiplies

    int qi = 0, qj = 0;
    for (int qt = 0; qt < WT; ++qt) {
        float s0 = 0.f, s1 = 0.f;
        #pragma unroll
        for (int dd = 0; dd < HDIM; ++dd) {
            const float qv = qTh[dd * TP + qt];
            s0 = fmaf(qv, kk1[dd], s0);
            s1 = fmaf(qv, kk2[dd], s1);
        }
        const int iq13 = (qi + qj) * 13;
        if (++qj == WS) { qj = 0; ++qi; }
        s0 = s0 * SQ + pos_s[iq13 + ij1];
        s1 = has2 ? (s1 * SQ + pos_s[iq13 + ij2]) : -1e30f;

        float m = fmaxf(s0, s1);
        #pragma unroll
        for (int o = 16; o; o >>= 1) m = fmaxf(m, __shfl_xor_sync(0xFFFFFFFFu, m, o));
        const float e0 = __expf(s0 - m);
        const float e1 = has2 ? __expf(s1 - m) : 0.f;
        float sum = e0 + e1;
        #pragma unroll
        for (int o = 16; o; o >>= 1) sum += __shfl_xor_sync(0xFFFFFFFFu, sum, o);
        const float inv = __fdividef(1.f, sum);
        const float p0 = e0 * inv;
        const float p1 = e1 * inv;

        float o_acc = 0.f;
        #pragma unroll
        for (int j = 0; j < 32; ++j) {
            const float pj = __shfl_sync(0xFFFFFFFFu, p0, j);
            o_acc = fmaf(pj, vh[j * HDIM + lane], o_acc);
        }
        #pragma unroll
        for (int j = 0; j < 17; ++j) {
            const float pj = __shfl_sync(0xFFFFFFFFu, p1, j);
            o_acc = fmaf(pj, vh[(j + 32) * HDIM + lane], o_acc);
        }

        const int row = base_tok + (qt / WS) * 56 + (qt % WS);
        __nv_bfloat16 oh, ol;
        split2(o_acc, oh, ol);
        g_ah[(size_t)row * CDIM + tid] = oh;
        g_al[(size_t)row * CDIM + tid] = ol;
    }
}

// ------------------------- host launcher -------------------------
extern "C" void kernel_launch(void* const* d_in, const int* in_sizes, int n_in,
                              void* d_out, int out_size)
{
    const float* x     = (const float*)d_in[0];
    const float* pos   = (const float*)d_in[1];
    const float* w_qkv = (const float*)d_in[2];
    const float* b_qkv = (const float*)d_in[3];
    const float* w_out = (const float*)d_in[4];
    const float* b_out = (const float*)d_in[5];
    float* out = (float*)d_out;

    void *p_qkv, *p_xh, *p_xl, *p_ah, *p_al, *p_wqh, *p_wql, *p_woh, *p_wol;
    cudaGetSymbolAddress(&p_qkv, g_qkv);
    cudaGetSymbolAddress(&p_xh,  g_xh);
    cudaGetSymbolAddress(&p_xl,  g_xl);
    cudaGetSymbolAddress(&p_ah,  g_ah);
    cudaGetSymbolAddress(&p_al,  g_al);
    cudaGetSymbolAddress(&p_wqh, g_wqT_h);
    cudaGetSymbolAddress(&p_wql, g_wqT_l);
    cudaGetSymbolAddress(&p_woh, g_woT_h);
    cudaGetSymbolAddress(&p_wol, g_woT_l);

    cudaFuncSetAttribute(gemm_split_kernel, cudaFuncAttributeMaxDynamicSharedMemorySize, GEMM_SMEM);
    cudaFuncSetAttribute(attn_kernel,       cudaFuncAttributeMaxDynamicSharedMemorySize, ATT_SMEM);

    // P0: splits
    split_x_kernel<<<2048, 256>>>(x);
    split_wT_kernel<<<(QKVN * CDIM) / 256, 256>>>(w_qkv, (__nv_bfloat16*)p_wqh, (__nv_bfloat16*)p_wql, QKVN);
    split_wT_kernel<<<(CDIM * CDIM) / 256, 256>>>(w_out, (__nv_bfloat16*)p_woh, (__nv_bfloat16*)p_wol, CDIM);

    // K1: QKV GEMM  [200704 x 768]
    gemm_split_kernel<<<dim3(QKVN / BN, TOK / BM), 256, GEMM_SMEM>>>(
        (const __nv_bfloat16*)p_xh, (const __nv_bfloat16*)p_xl,
        (const __nv_bfloat16*)p_wqh, (const __nv_bfloat16*)p_wql,
        b_qkv, (float*)p_qkv, QKVN);

    // K2: windowed attention
    attn_kernel<<<4096, 256, ATT_SMEM>>>(pos);

    // K3: output projection  [200704 x 256]
    gemm_split_kernel<<<dim3(CDIM / BN, TOK / BM), 256, GEMM_SMEM>>>(
        (const __nv_bfloat16*)p_ah, (const __nv_bfloat16*)p_al,
        (const __nv_bfloat16*)p_woh, (const __nv_bfloat16*)p_wol,
        b_out, out, CDIM);
}

// round 8
// speedup vs baseline: 3.6374x; 1.6864x over previous
#include <cuda_runtime.h>
#include <cuda_bf16.h>
#include <cstdint>

#define TOK   200704            // 64*56*56 tokens
#define CDIM  256
#define QKVN  768
#define WS    7
#define WT    49
#define NHEAD 8
#define HDIM  32

// ------------------------- scratch (device globals) -------------------------
__device__ float          g_qkv[154140672];          // [TOK][768] fp32
__device__ __nv_bfloat16  g_xh [51380224];           // [TOK][256] x hi
__device__ __nv_bfloat16  g_xl [51380224];           // [TOK][256] x lo
__device__ __nv_bfloat16  g_ah [51380224];           // attn out hi
__device__ __nv_bfloat16  g_al [51380224];           // attn out lo
__device__ __nv_bfloat16  g_wqT_h[196608];           // WqkvT [768][256] K-major
__device__ __nv_bfloat16  g_wqT_l[196608];
__device__ __nv_bfloat16  g_woT_h[65536];            // WoutT [256][256] K-major
__device__ __nv_bfloat16  g_woT_l[65536];

// ------------------------- helpers -------------------------
__device__ __forceinline__ uint32_t smem_u32(const void* p) {
    uint32_t a;
    asm("{ .reg .u64 t; cvta.to.shared.u64 t, %1; cvt.u32.u64 %0, t; }" : "=r"(a) : "l"(p));
    return a;
}
#define CP_ASYNC16(dst, src) \
    asm volatile("cp.async.cg.shared.global [%0], [%1], 16;\n" :: "r"(dst), "l"(src))
#define CP_COMMIT() asm volatile("cp.async.commit_group;\n" ::: "memory")

__device__ __forceinline__ void ldsm4(uint32_t addr, uint32_t* r) {
    asm volatile("ldmatrix.sync.aligned.m8n8.x4.shared.b16 {%0,%1,%2,%3}, [%4];"
        : "=r"(r[0]), "=r"(r[1]), "=r"(r[2]), "=r"(r[3]) : "r"(addr));
}
__device__ __forceinline__ void mma16816(float* c, const uint32_t* a, const uint32_t* b) {
    asm volatile(
        "mma.sync.aligned.m16n8k16.row.col.f32.bf16.bf16.f32 "
        "{%0,%1,%2,%3}, {%4,%5,%6,%7}, {%8,%9}, {%0,%1,%2,%3};"
        : "+f"(c[0]), "+f"(c[1]), "+f"(c[2]), "+f"(c[3])
        : "r"(a[0]), "r"(a[1]), "r"(a[2]), "r"(a[3]), "r"(b[0]), "r"(b[1]));
}
__device__ __forceinline__ uint32_t sw128(uint32_t row, uint32_t kb) {
    uint32_t off = (row << 7) + kb;
    return off ^ ((off >> 3) & 0x70);
}
__device__ __forceinline__ void split2(float v, __nv_bfloat16& h, __nv_bfloat16& l) {
    h = __float2bfloat16_rn(v);
    l = __float2bfloat16_rn(v - __bfloat162float(h));
}

// ------------------------- P0: split kernels -------------------------
__global__ void split_x_kernel(const float* __restrict__ x) {
    size_t n4 = (size_t)TOK * CDIM / 4;
    for (size_t i = (size_t)blockIdx.x * blockDim.x + threadIdx.x; i < n4;
         i += (size_t)gridDim.x * blockDim.x) {
        float4 v = ((const float4*)x)[i];
        __nv_bfloat16 h0,h1,h2,h3,l0,l1,l2,l3;
        split2(v.x,h0,l0); split2(v.y,h1,l1); split2(v.z,h2,l2); split2(v.w,h3,l3);
        ((__nv_bfloat162*)g_xh)[2*i]   = __nv_bfloat162(h0,h1);
        ((__nv_bfloat162*)g_xh)[2*i+1] = __nv_bfloat162(h2,h3);
        ((__nv_bfloat162*)g_xl)[2*i]   = __nv_bfloat162(l0,l1);
        ((__nv_bfloat162*)g_xl)[2*i+1] = __nv_bfloat162(l2,l3);
    }
}
// out[n*256 + k] = split(w[k*N + n])   (transpose to [N][K] K-major)
__global__ void split_wT_kernel(const float* __restrict__ w,
                                __nv_bfloat16* __restrict__ oh,
                                __nv_bfloat16* __restrict__ ol, int N) {
    int idx = blockIdx.x * blockDim.x + threadIdx.x;
    if (idx >= N * CDIM) return;
    int n = idx >> 8, k = idx & 255;
    __nv_bfloat16 h, l;
    split2(w[(size_t)k * N + n], h, l);
    oh[(size_t)n * CDIM + k] = h;
    ol[(size_t)n * CDIM + k] = l;
}

// ------------------------- split-bf16 GEMM on mma.sync -------------------------
#define BM 128
#define BN 128
#define BK 64
#define NSTAGE 3
#define AH_OFF 0
#define AL_OFF 16384
#define BH_OFF 32768
#define BL_OFF 49152
#define STAGE_BYTES 65536
#define GEMM_SMEM (NSTAGE * STAGE_BYTES)

__device__ __forceinline__ void load_chunk(uint32_t sb, int c,
    const __nv_bfloat16* __restrict__ Ah, const __nv_bfloat16* __restrict__ Al,
    const __nv_bfloat16* __restrict__ Bh, const __nv_bfloat16* __restrict__ Bl,
    int m0, int n0, int tid)
{
    #pragma unroll
    for (int i = 0; i < 4; ++i) {
        int t = tid + i * 256, r = t >> 3, seg = t & 7;
        uint32_t dst = sb + sw128(r, seg * 16);
        size_t ga = (size_t)(m0 + r) * CDIM + c * BK + seg * 8;
        CP_ASYNC16(dst + AH_OFF, Ah + ga);
        CP_ASYNC16(dst + AL_OFF, Al + ga);
        size_t gb = (size_t)(n0 + r) * CDIM + c * BK + seg * 8;
        CP_ASYNC16(dst + BH_OFF, Bh + gb);
        CP_ASYNC16(dst + BL_OFF, Bl + gb);
    }
    CP_COMMIT();
}

__global__ __launch_bounds__(256, 1)
void gemm_split_kernel(const __nv_bfloat16* __restrict__ Ah, const __nv_bfloat16* __restrict__ Al,
                       const __nv_bfloat16* __restrict__ Bh, const __nv_bfloat16* __restrict__ Bl,
                       const float* __restrict__ bias, float* __restrict__ outp, int out_ld)
{
    extern __shared__ __align__(1024) char smem[];
    const uint32_t smb = smem_u32(smem);
    const int tid  = threadIdx.x;
    const int lane = tid & 31, wid = tid >> 5;
    const int wm = wid & 3, wn = wid >> 2;              // 4 M-warps x 2 N-warps
    const int n0 = blockIdx.x * BN;
    const int m0 = blockIdx.y * BM;

    const int li = lane & 7, lg = lane >> 3;
    const int aRowOff = ((lg & 1) << 3) + li;
    const int aKoff   = (lg >> 1) << 4;
    const int bRowOff = ((lg >> 1) << 3) + li;
    const int bKoff   = (lg & 1) << 4;

    float acc[2][8][4];
    #pragma unroll
    for (int a = 0; a < 2; ++a)
        #pragma unroll
        for (int b = 0; b < 8; ++b)
            #pragma unroll
            for (int cc = 0; cc < 4; ++cc) acc[a][b][cc] = 0.f;

    load_chunk(smb + 0 * STAGE_BYTES, 0, Ah, Al, Bh, Bl, m0, n0, tid);
    load_chunk(smb + 1 * STAGE_BYTES, 1, Ah, Al, Bh, Bl, m0, n0, tid);

    #pragma unroll 1
    for (int c = 0; c < 4; ++c) {
        if (c < 3) asm volatile("cp.async.wait_group 1;\n" ::: "memory");
        else       asm volatile("cp.async.wait_group 0;\n" ::: "memory");
        __syncthreads();
        const uint32_t sb = smb + (uint32_t)(c % NSTAGE) * STAGE_BYTES;

        #pragma unroll
        for (int s = 0; s < 4; ++s) {
            const uint32_t kbA = (uint32_t)(s * 32 + aKoff);
            const uint32_t kbB = (uint32_t)(s * 32 + bKoff);
            uint32_t ah[2][4], al[2][4];
            #pragma unroll
            for (int mt = 0; mt < 2; ++mt) {
                const uint32_t arow = (uint32_t)(wm * 32 + mt * 16 + aRowOff);
                const uint32_t sw = sw128(arow, kbA);
                ldsm4(sb + AH_OFF + sw, ah[mt]);
                ldsm4(sb + AL_OFF + sw, al[mt]);
            }
            uint32_t bh[4][4], bl[4][4];
            #pragma unroll
            for (int nt = 0; nt < 4; ++nt) {
                const uint32_t brow = (uint32_t)(wn * 64 + nt * 16 + bRowOff);
                const uint32_t sw = sw128(brow, kbB);
                ldsm4(sb + BH_OFF + sw, bh[nt]);
                ldsm4(sb + BL_OFF + sw, bl[nt]);
            }
            #pragma unroll
            for (int mt = 0; mt < 2; ++mt)
                #pragma unroll
                for (int nt = 0; nt < 4; ++nt) {
                    mma16816(acc[mt][nt*2],   ah[mt], &bh[nt][0]);
                    mma16816(acc[mt][nt*2],   ah[mt], &bl[nt][0]);
                    mma16816(acc[mt][nt*2],   al[mt], &bh[nt][0]);
                    mma16816(acc[mt][nt*2+1], ah[mt], &bh[nt][2]);
                    mma16816(acc[mt][nt*2+1], ah[mt], &bl[nt][2]);
                    mma16816(acc[mt][nt*2+1], al[mt], &bh[nt][2]);
                }
        }
        if (c + 2 < 4)
            load_chunk(smb + (uint32_t)((c + 2) % NSTAGE) * STAGE_BYTES, c + 2,
                       Ah, Al, Bh, Bl, m0, n0, tid);
    }

    #pragma unroll
    for (int mt = 0; mt < 2; ++mt) {
        const int row = m0 + wm * 32 + mt * 16 + (lane >> 2);
        #pragma unroll
        for (int nt = 0; nt < 8; ++nt) {
            const int col = n0 + wn * 64 + nt * 8 + 2 * (lane & 3);
            const float b0 = __ldg(bias + col), b1 = __ldg(bias + col + 1);
            float2 v0 = make_float2(acc[mt][nt][0] + b0, acc[mt][nt][1] + b1);
            float2 v1 = make_float2(acc[mt][nt][2] + b0, acc[mt][nt][3] + b1);
            *(float2*)(outp + (size_t)row * out_ld + col)       = v0;
            *(float2*)(outp + (size_t)(row + 8) * out_ld + col) = v1;
        }
    }
}

// ------------------------- K2: windowed attention (4 heads/CTA, 2 warps/head) -------------------------
#define TP 52
#define HPC 4                                   // heads per CTA
// smem: qT[128][52] + kT[128][52] + v[4][49][32] + pos[169]
#define ATT_SMEM ((128*TP*2 + HPC*WT*HDIM + 169 + 7) * 4)

__global__ __launch_bounds__(256, 2)
void attn_kernel(const float* __restrict__ pos)
{
    extern __shared__ float smf[];
    float* qT    = smf;                          // [128][52]  (ch-local major)
    float* kT    = qT + 128*TP;                  // [128][52]
    float* v_s   = kT + 128*TP;                  // [4][49][32]
    float* pos_s = v_s + HPC*WT*HDIM;            // [169]

    const int tid = threadIdx.x;
    const int win = blockIdx.x >> 1;
    const int hh  = blockIdx.x & 1;              // head-half: heads hh*4 .. hh*4+3
    const int b = win >> 6, wi = (win >> 3) & 7, wj = win & 7;
    const int base_tok = b * 3136 + (wi * WS) * 56 + wj * WS;

    if (tid < 169) pos_s[tid] = pos[tid];

    // load phase: threads 0-127 load q+v, threads 128-255 load k
    {
        const int cl = tid & 127;                // local channel 0..127
        const bool isK = tid >= 128;
        #pragma unroll 7
        for (int t = 0; t < WT; ++t) {
            const int row = base_tok + (t / WS) * 56 + (t % WS);
            const float* rp = g_qkv + (size_t)row * QKVN;
            if (!isK) {
                qT[cl * TP + t] = rp[hh * 128 + cl];
                v_s[((cl >> 5) * WT + t) * HDIM + (cl & 31)] = rp[512 + hh * 128 + cl];
            } else {
                kT[cl * TP + t] = rp[256 + hh * 128 + cl];
            }
        }
    }
    __syncthreads();

    // compute phase: warp w -> head hl = w>>1, q-token half = w&1
    {
        const int lane = tid & 31;
        const int wid  = tid >> 5;
        const int hl   = wid >> 1;               // local head 0..3
        const int half = wid & 1;
        const int qs = half ? 25 : 0;
        const int qe = half ? WT : 25;

        const float* qTh = qT + hl * HDIM * TP;
        const float* kTh = kT + hl * HDIM * TP;
        const float* vh  = v_s + hl * WT * HDIM;

        const int j1 = lane;
        const bool has2 = (lane < 17);
        const int j2 = has2 ? lane + 32 : 0;

        float kk1[HDIM], kk2[HDIM];
        #pragma unroll
        for (int dd = 0; dd < HDIM; ++dd) {
            kk1[dd] = kTh[dd * TP + j1];
            kk2[dd] = kTh[dd * TP + j2];
        }
        const int ij1 = j1 / WS + j1 % WS;
        const int ij2 = j2 / WS + j2 % WS;
        const float SQ = 5.6568542494923806f;    // sqrt(32), reference multiplies

        const int ch = hh * 128 + hl * HDIM + lane;   // global output channel

        for (int qt = qs; qt < qe; ++qt) {
            float s0 = 0.f, s1 = 0.f;
            #pragma unroll
            for (int dd = 0; dd < HDIM; ++dd) {
                const float qv = qTh[dd * TP + qt];
                s0 = fmaf(qv, kk1[dd], s0);
                s1 = fmaf(qv, kk2[dd], s1);
            }
            const int iq13 = (qt / WS + qt % WS) * 13;
            s0 = s0 * SQ + pos_s[iq13 + ij1];
            s1 = has2 ? (s1 * SQ + pos_s[iq13 + ij2]) : -1e30f;

            float m = fmaxf(s0, s1);
            #pragma unroll
            for (int o = 16; o; o >>= 1) m = fmaxf(m, __shfl_xor_sync(0xFFFFFFFFu, m, o));
            const float e0 = __expf(s0 - m);
            const float e1 = has2 ? __expf(s1 - m) : 0.f;
            float sum = e0 + e1;
            #pragma unroll
            for (int o = 16; o; o >>= 1) sum += __shfl_xor_sync(0xFFFFFFFFu, sum, o);
            const float inv = __fdividef(1.f, sum);
            const float p0 = e0 * inv;
            const float p1 = e1 * inv;

            float o_acc = 0.f;
            #pragma unroll
            for (int j = 0; j < 32; ++j) {
                const float pj = __shfl_sync(0xFFFFFFFFu, p0, j);
                o_acc = fmaf(pj, vh[j * HDIM + lane], o_acc);
            }
            #pragma unroll
            for (int j = 0; j < 17; ++j) {
                const float pj = __shfl_sync(0xFFFFFFFFu, p1, j);
                o_acc = fmaf(pj, vh[(j + 32) * HDIM + lane], o_acc);
            }

            const int row = base_tok + (qt / WS) * 56 + (qt % WS);
            __nv_bfloat16 oh, ol;
            split2(o_acc, oh, ol);
            g_ah[(size_t)row * CDIM + ch] = oh;
            g_al[(size_t)row * CDIM + ch] = ol;
        }
    }
}

// ------------------------- host launcher -------------------------
extern "C" void kernel_launch(void* const* d_in, const int* in_sizes, int n_in,
                              void* d_out, int out_size)
{
    const float* x     = (const float*)d_in[0];
    const float* pos   = (const float*)d_in[1];
    const float* w_qkv = (const float*)d_in[2];
    const float* b_qkv = (const float*)d_in[3];
    const float* w_out = (const float*)d_in[4];
    const float* b_out = (const float*)d_in[5];
    float* out = (float*)d_out;

    void *p_qkv, *p_xh, *p_xl, *p_ah, *p_al, *p_wqh, *p_wql, *p_woh, *p_wol;
    cudaGetSymbolAddress(&p_qkv, g_qkv);
    cudaGetSymbolAddress(&p_xh,  g_xh);
    cudaGetSymbolAddress(&p_xl,  g_xl);
    cudaGetSymbolAddress(&p_ah,  g_ah);
    cudaGetSymbolAddress(&p_al,  g_al);
    cudaGetSymbolAddress(&p_wqh, g_wqT_h);
    cudaGetSymbolAddress(&p_wql, g_wqT_l);
    cudaGetSymbolAddress(&p_woh, g_woT_h);
    cudaGetSymbolAddress(&p_wol, g_woT_l);

    cudaFuncSetAttribute(gemm_split_kernel, cudaFuncAttributeMaxDynamicSharedMemorySize, GEMM_SMEM);
    cudaFuncSetAttribute(attn_kernel,       cudaFuncAttributeMaxDynamicSharedMemorySize, ATT_SMEM);

    // P0: splits
    split_x_kernel<<<2048, 256>>>(x);
    split_wT_kernel<<<(QKVN * CDIM) / 256, 256>>>(w_qkv, (__nv_bfloat16*)p_wqh, (__nv_bfloat16*)p_wql, QKVN);
    split_wT_kernel<<<(CDIM * CDIM) / 256, 256>>>(w_out, (__nv_bfloat16*)p_woh, (__nv_bfloat16*)p_wol, CDIM);

    // K1: QKV GEMM  [200704 x 768]
    gemm_split_kernel<<<dim3(QKVN / BN, TOK / BM), 256, GEMM_SMEM>>>(
        (const __nv_bfloat16*)p_xh, (const __nv_bfloat16*)p_xl,
        (const __nv_bfloat16*)p_wqh, (const __nv_bfloat16*)p_wql,
        b_qkv, (float*)p_qkv, QKVN);

    // K2: windowed attention (2 CTAs per window)
    attn_kernel<<<8192, 256, ATT_SMEM>>>(pos);

    // K3: output projection  [200704 x 256]
    gemm_split_kernel<<<dim3(CDIM / BN, TOK / BM), 256, GEMM_SMEM>>>(
        (const __nv_bfloat16*)p_ah, (const __nv_bfloat16*)p_al,
        (const __nv_bfloat16*)p_woh, (const __nv_bfloat16*)p_wol,
        b_out, out, CDIM);
}